// round 11
// baseline (speedup 1.0000x reference)
#include <cuda_runtime.h>
#include <cuda_fp16.h>
#include <cstdint>

#define N_NODES 1000000
#define N_EDGES 5000000
#define N_LABEL 2000000
#define FDIM    16

#define SCAN_CHUNK 2048
#define NB ((N_NODES + SCAN_CHUNK - 1) / SCAN_CHUNK)   // 489

// Scratch (device globals — allocation is forbidden)
__device__ int      g_deg [N_NODES];
__device__ int      g_off [N_NODES + 1];
__device__ int      g_cur [N_NODES];
__device__ int      g_csr [N_EDGES];
__device__ int      g_bsum[NB];
__device__ float    g_dinv[N_NODES];
__device__ unsigned g_msg1[N_NODES * 8];   // layer-1 messages, half2-packed
__device__ unsigned g_msg2[N_NODES * 8];   // layer-2 messages, half2-packed
__device__ float    g_pA  [N_NODES];       // dot(z_i, fc_w[0:16])
__device__ float    g_pB  [N_NODES];       // dot(z_i, fc_w[16:32])

// ---------------------------------------------------------------------------
__global__ void k_count(const int4* __restrict__ dst4) {
    int e = blockIdx.x * blockDim.x + threadIdx.x;
    if (e < N_EDGES / 4) {
        int4 d = dst4[e];
        atomicAdd(&g_deg[d.x], 1);
        atomicAdd(&g_deg[d.y], 1);
        atomicAdd(&g_deg[d.z], 1);
        atomicAdd(&g_deg[d.w], 1);
    }
}

__global__ void k_dinv() {
    int i = blockIdx.x * blockDim.x + threadIdx.x;
    if (i < N_NODES) g_dinv[i] = rsqrtf((float)(g_deg[i] + 1));  // +1 self loop
}

// ---------------------------------------------------------------------------
// 3-phase exclusive scan of g_deg into g_off.
__global__ void k_scan1() {
    __shared__ int s[256];
    int b = blockIdx.x, t = threadIdx.x;
    int base = b * SCAN_CHUNK + t * 8;
    int v[8], sum = 0;
    #pragma unroll
    for (int q = 0; q < 8; q++) {
        int idx = base + q;
        int d = (idx < N_NODES) ? g_deg[idx] : 0;
        v[q] = sum; sum += d;
    }
    s[t] = sum; __syncthreads();
    for (int o = 1; o < 256; o <<= 1) {
        int x = (t >= o) ? s[t - o] : 0;
        __syncthreads();
        s[t] += x;
        __syncthreads();
    }
    int excl = (t > 0) ? s[t - 1] : 0;
    #pragma unroll
    for (int q = 0; q < 8; q++) {
        int idx = base + q;
        if (idx < N_NODES) g_off[idx] = v[q] + excl;
    }
    if (t == 255) g_bsum[b] = s[255];
}

__global__ void k_scan2() {
    __shared__ int s[512];
    int t = threadIdx.x;
    s[t] = (t < NB) ? g_bsum[t] : 0;
    __syncthreads();
    for (int o = 1; o < 512; o <<= 1) {
        int x = (t >= o) ? s[t - o] : 0;
        __syncthreads();
        s[t] += x;
        __syncthreads();
    }
    if (t < NB) g_bsum[t] = (t > 0) ? s[t - 1] : 0;   // exclusive
}

__global__ void k_scan3() {
    int i = blockIdx.x * blockDim.x + threadIdx.x;
    if (i < N_NODES) {
        int o = g_off[i] + g_bsum[i >> 11];
        g_off[i] = o;
        g_cur[i] = o;
    }
    if (i == 0) g_off[N_NODES] = N_EDGES;
}

__global__ void k_fill(const int4* __restrict__ src4, const int4* __restrict__ dst4) {
    int e = blockIdx.x * blockDim.x + threadIdx.x;
    if (e >= N_EDGES / 4) return;
    int4 s = src4[e];
    int4 d = dst4[e];
    g_csr[atomicAdd(&g_cur[d.x], 1)] = s.x;
    g_csr[atomicAdd(&g_cur[d.y], 1)] = s.y;
    g_csr[atomicAdd(&g_cur[d.z], 1)] = s.z;
    g_csr[atomicAdd(&g_cur[d.w], 1)] = s.w;
}

// ---------------------------------------------------------------------------
// K-mm1: msg1[i] = (embed[x[i]] @ W1) * dinv[i]  (half2-packed, 32 B/node)
__global__ void k_mm1(const int* __restrict__ x,
                      const float* __restrict__ embed,
                      const float* __restrict__ W1) {
    __shared__ float Ws[FDIM][FDIM];
    if (threadIdx.x < 256) {
        int k = threadIdx.x >> 4, j = threadIdx.x & 15;
        Ws[k][j] = W1[threadIdx.x];
    }
    __syncthreads();

    int i = blockIdx.x * blockDim.x + threadIdx.x;
    if (i >= N_NODES) return;

    const float4* rp = (const float4*)(embed + (size_t)x[i] * FDIM);
    float4 r0 = rp[0], r1 = rp[1], r2 = rp[2], r3 = rp[3];
    float row[FDIM] = {r0.x,r0.y,r0.z,r0.w, r1.x,r1.y,r1.z,r1.w,
                       r2.x,r2.y,r2.z,r2.w, r3.x,r3.y,r3.z,r3.w};
    float dv = g_dinv[i];
    float out[FDIM];
    #pragma unroll
    for (int j = 0; j < FDIM; j++) {
        float acc = 0.f;
        #pragma unroll
        for (int k = 0; k < FDIM; k++) acc = fmaf(row[k], Ws[k][j], acc);
        out[j] = acc * dv;
    }
    __half2 h[8];
    #pragma unroll
    for (int q = 0; q < 8; q++) h[q] = __floats2half2_rn(out[2*q], out[2*q+1]);
    uint4* mp = (uint4*)(g_msg1 + (size_t)i * 8);
    mp[0] = make_uint4(*(unsigned*)&h[0], *(unsigned*)&h[1], *(unsigned*)&h[2], *(unsigned*)&h[3]);
    mp[1] = make_uint4(*(unsigned*)&h[4], *(unsigned*)&h[5], *(unsigned*)&h[6], *(unsigned*)&h[7]);
}

// ---------------------------------------------------------------------------
__device__ __forceinline__ void acc_h4(float4& a, uint2 m) {
    float2 f0 = __half22float2(*(__half2*)&m.x);
    float2 f1 = __half22float2(*(__half2*)&m.y);
    a.x += f0.x; a.y += f0.y; a.z += f1.x; a.w += f1.y;
}

// Dual-node gather: interleaves nodeA's and nodeB's batch-4 waves in ONE loop
// so 8 csr loads + 8 msg loads are in flight per iteration (2x MLP).
// Safe clamped indices; predicated accumulation.
__device__ __forceinline__ void gather2(const uint2* __restrict__ M, int t,
                                        int oA0, int oA1, int oB0, int oB1,
                                        float4& accA, float4& accB) {
    int lastA = oA1 - 1, lastB = oB1 - 1;
    int nA = oA1 - oA0, nB = oB1 - oB0;
    int iters = (max(nA, nB) + 3) >> 2;
    int jA = oA0, jB = oB0;
    for (int it = 0; it < iters; it++) {
        int ia[4], ib[4];
        #pragma unroll
        for (int q = 0; q < 4; q++) ia[q] = g_csr[max(min(jA + q, lastA), 0)];
        #pragma unroll
        for (int q = 0; q < 4; q++) ib[q] = g_csr[max(min(jB + q, lastB), 0)];
        uint2 ma[4], mb[4];
        #pragma unroll
        for (int q = 0; q < 4; q++) ma[q] = M[(size_t)ia[q] * 4 + t];
        #pragma unroll
        for (int q = 0; q < 4; q++) mb[q] = M[(size_t)ib[q] * 4 + t];
        #pragma unroll
        for (int q = 0; q < 4; q++) {
            if (jA + q < oA1) acc_h4(accA, ma[q]);
            if (jB + q < oB1) acc_h4(accB, mb[q]);
        }
        jA += 4; jB += 4;
    }
}

// K-gather1 fused with layer-2 matmul. 2 nodes per 4-thread group.
// Block = 256 threads = 64 groups = 128 nodes. Grid = ceil(1e6/128) = 7813;
// in the last block hasB is false for ALL threads (warp-uniform).
__global__ void k_gather_mm2(const float* __restrict__ W2,
                             const float* __restrict__ b1) {
    __shared__ float Ws[FDIM][FDIM];
    __shared__ float bs[FDIM];
    if (threadIdx.x < 256) {
        int k = threadIdx.x >> 4, j = threadIdx.x & 15;
        Ws[k][j] = W2[threadIdx.x];
        if (threadIdx.x < FDIM) bs[threadIdx.x] = b1[threadIdx.x];
    }
    __syncthreads();

    int t     = threadIdx.x & 3;
    int gbase = (threadIdx.x & 31) & ~3;
    int nodeA = blockIdx.x * 128 + (threadIdx.x >> 2);
    int nodeB = nodeA + 64;
    bool hasB = (nodeB < N_NODES);

    int oA0 = g_off[nodeA], oA1 = g_off[nodeA + 1];
    int oB0 = 0, oB1 = 0;
    if (hasB) { oB0 = g_off[nodeB]; oB1 = g_off[nodeB + 1]; }

    const uint2* M = (const uint2*)g_msg1;
    float4 accA = make_float4(0.f, 0.f, 0.f, 0.f);
    float4 accB = make_float4(0.f, 0.f, 0.f, 0.f);
    acc_h4(accA, M[(size_t)nodeA * 4 + t]);
    if (hasB) acc_h4(accB, M[(size_t)nodeB * 4 + t]);

    gather2(M, t, oA0, oA1, oB0, oB1, accA, accB);

    // --- node A epilogue ---
    {
        float dv = g_dinv[nodeA];
        float h[4];
        h[0] = fmaxf(fmaf(dv, accA.x, bs[4*t + 0]), 0.f);
        h[1] = fmaxf(fmaf(dv, accA.y, bs[4*t + 1]), 0.f);
        h[2] = fmaxf(fmaf(dv, accA.z, bs[4*t + 2]), 0.f);
        h[3] = fmaxf(fmaf(dv, accA.w, bs[4*t + 3]), 0.f);
        float o[4] = {0.f, 0.f, 0.f, 0.f};
        #pragma unroll
        for (int k = 0; k < FDIM; k++) {
            float hk = __shfl_sync(0xFFFFFFFFu, h[k & 3], gbase + (k >> 2));
            o[0] = fmaf(hk, Ws[k][4*t + 0], o[0]);
            o[1] = fmaf(hk, Ws[k][4*t + 1], o[1]);
            o[2] = fmaf(hk, Ws[k][4*t + 2], o[2]);
            o[3] = fmaf(hk, Ws[k][4*t + 3], o[3]);
        }
        __half2 p0 = __floats2half2_rn(o[0] * dv, o[1] * dv);
        __half2 p1 = __floats2half2_rn(o[2] * dv, o[3] * dv);
        ((uint2*)g_msg2)[(size_t)nodeA * 4 + t] =
            make_uint2(*(unsigned*)&p0, *(unsigned*)&p1);
    }
    // --- node B epilogue ---
    if (hasB) {
        float dv = g_dinv[nodeB];
        float h[4];
        h[0] = fmaxf(fmaf(dv, accB.x, bs[4*t + 0]), 0.f);
        h[1] = fmaxf(fmaf(dv, accB.y, bs[4*t + 1]), 0.f);
        h[2] = fmaxf(fmaf(dv, accB.z, bs[4*t + 2]), 0.f);
        h[3] = fmaxf(fmaf(dv, accB.w, bs[4*t + 3]), 0.f);
        float o[4] = {0.f, 0.f, 0.f, 0.f};
        #pragma unroll
        for (int k = 0; k < FDIM; k++) {
            float hk = __shfl_sync(0xFFFFFFFFu, h[k & 3], gbase + (k >> 2));
            o[0] = fmaf(hk, Ws[k][4*t + 0], o[0]);
            o[1] = fmaf(hk, Ws[k][4*t + 1], o[1]);
            o[2] = fmaf(hk, Ws[k][4*t + 2], o[2]);
            o[3] = fmaf(hk, Ws[k][4*t + 3], o[3]);
        }
        __half2 p0 = __floats2half2_rn(o[0] * dv, o[1] * dv);
        __half2 p1 = __floats2half2_rn(o[2] * dv, o[3] * dv);
        ((uint2*)g_msg2)[(size_t)nodeB * 4 + t] =
            make_uint2(*(unsigned*)&p0, *(unsigned*)&p1);
    }
}

// K-gather2 fused with final FC partials, 2 nodes per group.
__global__ void k_gather_z(const float* __restrict__ b2,
                           const float* __restrict__ fc_w) {
    __shared__ float bs[FDIM];
    __shared__ float fw[32];
    if (threadIdx.x < FDIM) bs[threadIdx.x] = b2[threadIdx.x];
    if (threadIdx.x < 32)   fw[threadIdx.x] = fc_w[threadIdx.x];
    __syncthreads();

    int t     = threadIdx.x & 3;
    int nodeA = blockIdx.x * 128 + (threadIdx.x >> 2);
    int nodeB = nodeA + 64;
    bool hasB = (nodeB < N_NODES);

    int oA0 = g_off[nodeA], oA1 = g_off[nodeA + 1];
    int oB0 = 0, oB1 = 0;
    if (hasB) { oB0 = g_off[nodeB]; oB1 = g_off[nodeB + 1]; }

    const uint2* M = (const uint2*)g_msg2;
    float4 accA = make_float4(0.f, 0.f, 0.f, 0.f);
    float4 accB = make_float4(0.f, 0.f, 0.f, 0.f);
    acc_h4(accA, M[(size_t)nodeA * 4 + t]);
    if (hasB) acc_h4(accB, M[(size_t)nodeB * 4 + t]);

    gather2(M, t, oA0, oA1, oB0, oB1, accA, accB);

    // --- node A ---
    {
        float dv = g_dinv[nodeA];
        float z0 = fmaf(dv, accA.x, bs[4*t + 0]);
        float z1 = fmaf(dv, accA.y, bs[4*t + 1]);
        float z2 = fmaf(dv, accA.z, bs[4*t + 2]);
        float z3 = fmaf(dv, accA.w, bs[4*t + 3]);
        float pa = z0*fw[4*t] + z1*fw[4*t+1] + z2*fw[4*t+2] + z3*fw[4*t+3];
        float pb = z0*fw[16+4*t] + z1*fw[16+4*t+1] + z2*fw[16+4*t+2] + z3*fw[16+4*t+3];
        pa += __shfl_xor_sync(0xFFFFFFFFu, pa, 1);
        pa += __shfl_xor_sync(0xFFFFFFFFu, pa, 2);
        pb += __shfl_xor_sync(0xFFFFFFFFu, pb, 1);
        pb += __shfl_xor_sync(0xFFFFFFFFu, pb, 2);
        if (t == 0) { g_pA[nodeA] = pa; g_pB[nodeA] = pb; }
    }
    // --- node B ---
    if (hasB) {
        float dv = g_dinv[nodeB];
        float z0 = fmaf(dv, accB.x, bs[4*t + 0]);
        float z1 = fmaf(dv, accB.y, bs[4*t + 1]);
        float z2 = fmaf(dv, accB.z, bs[4*t + 2]);
        float z3 = fmaf(dv, accB.w, bs[4*t + 3]);
        float pa = z0*fw[4*t] + z1*fw[4*t+1] + z2*fw[4*t+2] + z3*fw[4*t+3];
        float pb = z0*fw[16+4*t] + z1*fw[16+4*t+1] + z2*fw[16+4*t+2] + z3*fw[16+4*t+3];
        pa += __shfl_xor_sync(0xFFFFFFFFu, pa, 1);
        pa += __shfl_xor_sync(0xFFFFFFFFu, pa, 2);
        pb += __shfl_xor_sync(0xFFFFFFFFu, pb, 1);
        pb += __shfl_xor_sync(0xFFFFFFFFu, pb, 2);
        if (t == 0) { g_pA[nodeB] = pa; g_pB[nodeB] = pb; }
    }
}

// ---------------------------------------------------------------------------
// K-predict: out[e] = pA[la[e]] + pB[lb[e]] + fc_b
__global__ void k_predict(const int* __restrict__ la,
                          const int* __restrict__ lb,
                          const float* __restrict__ fc_b,
                          float* __restrict__ out) {
    int e = blockIdx.x * blockDim.x + threadIdx.x;
    if (e >= N_LABEL) return;
    float fb = __ldg(fc_b);
    out[e] = g_pA[la[e]] + g_pB[lb[e]] + fb;
}

// ---------------------------------------------------------------------------
extern "C" void kernel_launch(void* const* d_in, const int* in_sizes, int n_in,
                              void* d_out, int out_size) {
    const int*   x     = (const int*)  d_in[0];
    const int*   ei    = (const int*)  d_in[1];
    const int*   eli   = (const int*)  d_in[2];
    const float* embed = (const float*)d_in[3];
    const float* W1    = (const float*)d_in[4];
    const float* b1    = (const float*)d_in[5];
    const float* W2    = (const float*)d_in[6];
    const float* b2    = (const float*)d_in[7];
    const float* fc_w  = (const float*)d_in[8];
    const float* fc_b  = (const float*)d_in[9];
    float*       out   = (float*)d_out;

    const int4* e_src4 = (const int4*)ei;
    const int4* e_dst4 = (const int4*)(ei + N_EDGES);
    const int*  l_a    = eli;
    const int*  l_b    = eli + N_LABEL;

    const int TB = 256;
    int gN  = (N_NODES + TB - 1) / TB;
    int gE4 = (N_EDGES / 4 + TB - 1) / TB;
    int gL  = (N_LABEL + TB - 1) / TB;
    int gG2 = (N_NODES + 127) / 128;     // 7813 blocks, 2 nodes / 4-thread group

    static cudaStream_t s2 = nullptr;
    static cudaEvent_t  e1 = nullptr, e2 = nullptr;
    static void* degPtr = nullptr;
    if (!e1) {
        if (cudaStreamCreateWithFlags(&s2, cudaStreamNonBlocking) != cudaSuccess) s2 = nullptr;
        cudaEventCreateWithFlags(&e1, cudaEventDisableTiming);
        cudaEventCreateWithFlags(&e2, cudaEventDisableTiming);
        cudaGetSymbolAddress(&degPtr, g_deg);
    }

    cudaMemsetAsync(degPtr, 0, N_NODES * sizeof(int), 0);
    k_count<<<gE4, TB>>>(e_dst4);

    if (s2) {
        cudaEventRecord(e1, 0);
        cudaStreamWaitEvent(s2, e1, 0);
        k_dinv<<<gN, TB, 0, s2>>>();
        k_mm1 <<<gN, TB, 0, s2>>>(x, embed, W1);
        cudaEventRecord(e2, s2);
        k_scan1<<<NB, 256>>>();
        k_scan2<<<1, 512>>>();
        k_scan3<<<gN, TB>>>();
        k_fill <<<gE4, TB>>>(e_src4, e_dst4);
        cudaStreamWaitEvent(0, e2, 0);
    } else {
        k_dinv <<<gN, TB>>>();
        k_scan1<<<NB, 256>>>();
        k_scan2<<<1, 512>>>();
        k_scan3<<<gN, TB>>>();
        k_fill <<<gE4, TB>>>(e_src4, e_dst4);
        k_mm1  <<<gN, TB>>>(x, embed, W1);
    }

    k_gather_mm2<<<gG2, TB>>>(W2, b1);
    k_gather_z  <<<gG2, TB>>>(b2, fc_w);
    k_predict   <<<gL, TB>>>(l_a, l_b, fc_b, out);
}

// round 12
// speedup vs baseline: 1.2377x; 1.2377x over previous
#include <cuda_runtime.h>
#include <cuda_fp16.h>
#include <cstdint>

#define N_NODES 1000000
#define N_EDGES 5000000
#define N_LABEL 2000000
#define FDIM    16

#define SCAN_CHUNK 2048
#define NB ((N_NODES + SCAN_CHUNK - 1) / SCAN_CHUNK)   // 489

// Scratch (device globals — allocation is forbidden)
__device__ int      g_deg [N_NODES];
__device__ int      g_off [N_NODES + 1];
__device__ int      g_cur [N_NODES];
__device__ int      g_csr [N_EDGES];
__device__ int      g_bsum[NB];
__device__ float    g_dinv[N_NODES];
__device__ unsigned g_msg1[N_NODES * 8];   // layer-1 messages, half2-packed
__device__ unsigned g_msg2[N_NODES * 8];   // layer-2 messages, half2-packed
__device__ float    g_pA  [N_NODES];       // dot(z_i, fc_w[0:16])
__device__ float    g_pB  [N_NODES];       // dot(z_i, fc_w[16:32])

// ---------------------------------------------------------------------------
__global__ void k_count(const int4* __restrict__ dst4) {
    int e = blockIdx.x * blockDim.x + threadIdx.x;
    if (e < N_EDGES / 4) {
        int4 d = dst4[e];
        atomicAdd(&g_deg[d.x], 1);
        atomicAdd(&g_deg[d.y], 1);
        atomicAdd(&g_deg[d.z], 1);
        atomicAdd(&g_deg[d.w], 1);
    }
}

__global__ void k_dinv() {
    int i = blockIdx.x * blockDim.x + threadIdx.x;
    if (i < N_NODES) g_dinv[i] = rsqrtf((float)(g_deg[i] + 1));  // +1 self loop
}

// ---------------------------------------------------------------------------
// 3-phase exclusive scan of g_deg into g_off.
__global__ void k_scan1() {
    __shared__ int s[256];
    int b = blockIdx.x, t = threadIdx.x;
    int base = b * SCAN_CHUNK + t * 8;
    int v[8], sum = 0;
    #pragma unroll
    for (int q = 0; q < 8; q++) {
        int idx = base + q;
        int d = (idx < N_NODES) ? g_deg[idx] : 0;
        v[q] = sum; sum += d;
    }
    s[t] = sum; __syncthreads();
    for (int o = 1; o < 256; o <<= 1) {
        int x = (t >= o) ? s[t - o] : 0;
        __syncthreads();
        s[t] += x;
        __syncthreads();
    }
    int excl = (t > 0) ? s[t - 1] : 0;
    #pragma unroll
    for (int q = 0; q < 8; q++) {
        int idx = base + q;
        if (idx < N_NODES) g_off[idx] = v[q] + excl;
    }
    if (t == 255) g_bsum[b] = s[255];
}

__global__ void k_scan2() {
    __shared__ int s[512];
    int t = threadIdx.x;
    s[t] = (t < NB) ? g_bsum[t] : 0;
    __syncthreads();
    for (int o = 1; o < 512; o <<= 1) {
        int x = (t >= o) ? s[t - o] : 0;
        __syncthreads();
        s[t] += x;
        __syncthreads();
    }
    if (t < NB) g_bsum[t] = (t > 0) ? s[t - 1] : 0;   // exclusive
}

__global__ void k_scan3() {
    int i = blockIdx.x * blockDim.x + threadIdx.x;
    if (i < N_NODES) {
        int o = g_off[i] + g_bsum[i >> 11];
        g_off[i] = o;
        g_cur[i] = o;
    }
    if (i == 0) g_off[N_NODES] = N_EDGES;
}

__global__ void k_fill(const int4* __restrict__ src4, const int4* __restrict__ dst4) {
    int e = blockIdx.x * blockDim.x + threadIdx.x;
    if (e >= N_EDGES / 4) return;
    int4 s = src4[e];
    int4 d = dst4[e];
    g_csr[atomicAdd(&g_cur[d.x], 1)] = s.x;
    g_csr[atomicAdd(&g_cur[d.y], 1)] = s.y;
    g_csr[atomicAdd(&g_cur[d.z], 1)] = s.z;
    g_csr[atomicAdd(&g_cur[d.w], 1)] = s.w;
}

// ---------------------------------------------------------------------------
// K-mm1: msg1[i] = (embed[x[i]] @ W1) * dinv[i]  (half2-packed, 32 B/node)
__global__ void k_mm1(const int* __restrict__ x,
                      const float* __restrict__ embed,
                      const float* __restrict__ W1) {
    __shared__ float Ws[FDIM][FDIM];
    if (threadIdx.x < 256) {
        int k = threadIdx.x >> 4, j = threadIdx.x & 15;
        Ws[k][j] = W1[threadIdx.x];
    }
    __syncthreads();

    int i = blockIdx.x * blockDim.x + threadIdx.x;
    if (i >= N_NODES) return;

    const float4* rp = (const float4*)(embed + (size_t)x[i] * FDIM);
    float4 r0 = rp[0], r1 = rp[1], r2 = rp[2], r3 = rp[3];
    float row[FDIM] = {r0.x,r0.y,r0.z,r0.w, r1.x,r1.y,r1.z,r1.w,
                       r2.x,r2.y,r2.z,r2.w, r3.x,r3.y,r3.z,r3.w};
    float dv = g_dinv[i];
    float out[FDIM];
    #pragma unroll
    for (int j = 0; j < FDIM; j++) {
        float acc = 0.f;
        #pragma unroll
        for (int k = 0; k < FDIM; k++) acc = fmaf(row[k], Ws[k][j], acc);
        out[j] = acc * dv;
    }
    __half2 h[8];
    #pragma unroll
    for (int q = 0; q < 8; q++) h[q] = __floats2half2_rn(out[2*q], out[2*q+1]);
    uint4* mp = (uint4*)(g_msg1 + (size_t)i * 8);
    mp[0] = make_uint4(*(unsigned*)&h[0], *(unsigned*)&h[1], *(unsigned*)&h[2], *(unsigned*)&h[3]);
    mp[1] = make_uint4(*(unsigned*)&h[4], *(unsigned*)&h[5], *(unsigned*)&h[6], *(unsigned*)&h[7]);
}

// ---------------------------------------------------------------------------
// accumulate one uint4 (8 halfs) into 8 floats
__device__ __forceinline__ void acc_h8(float* a, uint4 m) {
    const unsigned* u = &m.x;
    #pragma unroll
    for (int q = 0; q < 4; q++) {
        float2 f = __half22float2(*(__half2*)&u[q]);
        a[2*q]     += f.x;
        a[2*q + 1] += f.y;
    }
}

// Gather core: 2 threads/node, uint4 loads (half the LDG instructions of the
// 4-thr/uint2 form), batches of 4 with clamped indices + predicated accumulate.
__device__ __forceinline__ void gather_acc8(float* acc, const uint4* __restrict__ M,
                                            int node, int t, int o0, int o1) {
    acc_h8(acc, M[(size_t)node * 2 + t]);          // self message

    int last = o1 - 1;
    for (int j = o0; j < o1; j += 4) {
        int j1 = min(j + 1, last), j2 = min(j + 2, last), j3 = min(j + 3, last);
        int s0 = g_csr[j],  s1 = g_csr[j1];
        int s2 = g_csr[j2], s3 = g_csr[j3];
        uint4 m0 = M[(size_t)s0 * 2 + t];
        uint4 m1 = M[(size_t)s1 * 2 + t];
        uint4 m2 = M[(size_t)s2 * 2 + t];
        uint4 m3 = M[(size_t)s3 * 2 + t];
        acc_h8(acc, m0);
        if (j + 1 < o1) acc_h8(acc, m1);
        if (j + 2 < o1) acc_h8(acc, m2);
        if (j + 3 < o1) acc_h8(acc, m3);
    }
}

// K-gather1 fused with layer-2 matmul. 2 threads/node, 128 nodes per block.
// 1e6 % 16 == 0 -> warp-uniform exit at the tail; shuffles safe.
__global__ void k_gather_mm2(const float* __restrict__ W2,
                             const float* __restrict__ b1) {
    __shared__ float Ws[FDIM][FDIM];
    __shared__ float bs[FDIM];
    if (threadIdx.x < 256) {
        int k = threadIdx.x >> 4, j = threadIdx.x & 15;
        Ws[k][j] = W2[threadIdx.x];
        if (threadIdx.x < FDIM) bs[threadIdx.x] = b1[threadIdx.x];
    }
    __syncthreads();

    int node  = blockIdx.x * 128 + (threadIdx.x >> 1);
    if (node >= N_NODES) return;                    // warp-uniform (1e6 % 16 == 0)
    int t     = threadIdx.x & 1;
    int gbase = (threadIdx.x & 31) & ~1;

    float acc[8] = {0.f,0.f,0.f,0.f,0.f,0.f,0.f,0.f};
    gather_acc8(acc, (const uint4*)g_msg1, node, t,
                g_off[node], g_off[node + 1]);

    float dv = g_dinv[node];
    float h[8];
    #pragma unroll
    for (int q = 0; q < 8; q++)
        h[q] = fmaxf(fmaf(dv, acc[q], bs[8*t + q]), 0.f);

    float o[8] = {0.f,0.f,0.f,0.f,0.f,0.f,0.f,0.f};
    #pragma unroll
    for (int k = 0; k < FDIM; k++) {
        float hk = __shfl_sync(0xFFFFFFFFu, h[k & 7], gbase + (k >> 3));
        #pragma unroll
        for (int q = 0; q < 8; q++)
            o[q] = fmaf(hk, Ws[k][8*t + q], o[q]);
    }
    __half2 p[4];
    #pragma unroll
    for (int q = 0; q < 4; q++)
        p[q] = __floats2half2_rn(o[2*q] * dv, o[2*q + 1] * dv);
    ((uint4*)g_msg2)[(size_t)node * 2 + t] =
        make_uint4(*(unsigned*)&p[0], *(unsigned*)&p[1],
                   *(unsigned*)&p[2], *(unsigned*)&p[3]);
}

// K-gather2 fused with final FC partials, 2 threads/node.
__global__ void k_gather_z(const float* __restrict__ b2,
                           const float* __restrict__ fc_w) {
    __shared__ float bs[FDIM];
    __shared__ float fw[32];
    if (threadIdx.x < FDIM) bs[threadIdx.x] = b2[threadIdx.x];
    if (threadIdx.x < 32)   fw[threadIdx.x] = fc_w[threadIdx.x];
    __syncthreads();

    int node = blockIdx.x * 128 + (threadIdx.x >> 1);
    if (node >= N_NODES) return;                    // warp-uniform
    int t    = threadIdx.x & 1;

    float acc[8] = {0.f,0.f,0.f,0.f,0.f,0.f,0.f,0.f};
    gather_acc8(acc, (const uint4*)g_msg2, node, t,
                g_off[node], g_off[node + 1]);

    float dv = g_dinv[node];
    float pa = 0.f, pb = 0.f;
    #pragma unroll
    for (int q = 0; q < 8; q++) {
        float z = fmaf(dv, acc[q], bs[8*t + q]);
        pa = fmaf(z, fw[8*t + q],      pa);
        pb = fmaf(z, fw[16 + 8*t + q], pb);
    }
    pa += __shfl_xor_sync(0xFFFFFFFFu, pa, 1);
    pb += __shfl_xor_sync(0xFFFFFFFFu, pb, 1);

    if (t == 0) {
        g_pA[node] = pa;
        g_pB[node] = pb;
    }
}

// ---------------------------------------------------------------------------
// K-predict: out[e] = pA[la[e]] + pB[lb[e]] + fc_b
__global__ void k_predict(const int* __restrict__ la,
                          const int* __restrict__ lb,
                          const float* __restrict__ fc_b,
                          float* __restrict__ out) {
    int e = blockIdx.x * blockDim.x + threadIdx.x;
    if (e >= N_LABEL) return;
    float fb = __ldg(fc_b);
    out[e] = g_pA[la[e]] + g_pB[lb[e]] + fb;
}

// ---------------------------------------------------------------------------
extern "C" void kernel_launch(void* const* d_in, const int* in_sizes, int n_in,
                              void* d_out, int out_size) {
    const int*   x     = (const int*)  d_in[0];
    const int*   ei    = (const int*)  d_in[1];
    const int*   eli   = (const int*)  d_in[2];
    const float* embed = (const float*)d_in[3];
    const float* W1    = (const float*)d_in[4];
    const float* b1    = (const float*)d_in[5];
    const float* W2    = (const float*)d_in[6];
    const float* b2    = (const float*)d_in[7];
    const float* fc_w  = (const float*)d_in[8];
    const float* fc_b  = (const float*)d_in[9];
    float*       out   = (float*)d_out;

    const int4* e_src4 = (const int4*)ei;
    const int4* e_dst4 = (const int4*)(ei + N_EDGES);
    const int*  l_a    = eli;
    const int*  l_b    = eli + N_LABEL;

    const int TB = 256;
    int gN  = (N_NODES + TB - 1) / TB;
    int gE4 = (N_EDGES / 4 + TB - 1) / TB;
    int gL  = (N_LABEL + TB - 1) / TB;
    int gG  = (N_NODES + 127) / 128;     // 7813 blocks, 2 thr/node

    static cudaStream_t s2 = nullptr;
    static cudaEvent_t  e1 = nullptr, e2 = nullptr;
    static void* degPtr = nullptr;
    if (!e1) {
        if (cudaStreamCreateWithFlags(&s2, cudaStreamNonBlocking) != cudaSuccess) s2 = nullptr;
        cudaEventCreateWithFlags(&e1, cudaEventDisableTiming);
        cudaEventCreateWithFlags(&e2, cudaEventDisableTiming);
        cudaGetSymbolAddress(&degPtr, g_deg);
    }

    cudaMemsetAsync(degPtr, 0, N_NODES * sizeof(int), 0);
    k_count<<<gE4, TB>>>(e_dst4);

    if (s2) {
        cudaEventRecord(e1, 0);
        cudaStreamWaitEvent(s2, e1, 0);
        k_dinv<<<gN, TB, 0, s2>>>();
        k_mm1 <<<gN, TB, 0, s2>>>(x, embed, W1);
        cudaEventRecord(e2, s2);
        k_scan1<<<NB, 256>>>();
        k_scan2<<<1, 512>>>();
        k_scan3<<<gN, TB>>>();
        k_fill <<<gE4, TB>>>(e_src4, e_dst4);
        cudaStreamWaitEvent(0, e2, 0);
    } else {
        k_dinv <<<gN, TB>>>();
        k_scan1<<<NB, 256>>>();
        k_scan2<<<1, 512>>>();
        k_scan3<<<gN, TB>>>();
        k_fill <<<gE4, TB>>>(e_src4, e_dst4);
        k_mm1  <<<gN, TB>>>(x, embed, W1);
    }

    k_gather_mm2<<<gG, TB>>>(W2, b1);
    k_gather_z  <<<gG, TB>>>(b2, fc_w);
    k_predict   <<<gL, TB>>>(l_a, l_b, fc_b, out);
}

// round 14
// speedup vs baseline: 1.2441x; 1.0052x over previous
#include <cuda_runtime.h>
#include <cuda_fp16.h>
#include <cstdint>

#define N_NODES 1000000
#define N_EDGES 5000000
#define N_LABEL 2000000
#define FDIM    16

#define SCAN_CHUNK 2048
#define NB ((N_NODES + SCAN_CHUNK - 1) / SCAN_CHUNK)   // 489

// Scratch (device globals — allocation is forbidden).
// g_deg relies on static zero-init + trailing re-zero each run (graph-invariant).
__device__ int      g_deg [N_NODES];
__device__ int      g_off [N_NODES + 1];
__device__ int      g_cur [N_NODES];
__device__ int      g_csr [N_EDGES];
__device__ int      g_bsum[NB];
__device__ float    g_dinv[N_NODES];
__device__ unsigned g_msg1[N_NODES * 8];   // layer-1 messages, half2-packed
__device__ unsigned g_msg2[N_NODES * 8];   // layer-2 messages, half2-packed
__device__ float    g_pA  [N_NODES];       // dot(z_i, fc_w[0:16])
__device__ float    g_pB  [N_NODES];       // dot(z_i, fc_w[16:32])

// ---------------------------------------------------------------------------
__global__ void k_count(const int4* __restrict__ dst4) {
    int e = blockIdx.x * blockDim.x + threadIdx.x;
    if (e < N_EDGES / 4) {
        int4 d = dst4[e];
        atomicAdd(&g_deg[d.x], 1);
        atomicAdd(&g_deg[d.y], 1);
        atomicAdd(&g_deg[d.z], 1);
        atomicAdd(&g_deg[d.w], 1);
    }
}

__global__ void k_dinv() {
    int i = blockIdx.x * blockDim.x + threadIdx.x;
    if (i < N_NODES) g_dinv[i] = rsqrtf((float)(g_deg[i] + 1));  // +1 self loop
}

// ---------------------------------------------------------------------------
// 3-phase exclusive scan of g_deg into g_off.
__global__ void k_scan1() {
    __shared__ int s[256];
    int b = blockIdx.x, t = threadIdx.x;
    int base = b * SCAN_CHUNK + t * 8;
    int v[8], sum = 0;
    #pragma unroll
    for (int q = 0; q < 8; q++) {
        int idx = base + q;
        int d = (idx < N_NODES) ? g_deg[idx] : 0;
        v[q] = sum; sum += d;
    }
    s[t] = sum; __syncthreads();
    for (int o = 1; o < 256; o <<= 1) {
        int x = (t >= o) ? s[t - o] : 0;
        __syncthreads();
        s[t] += x;
        __syncthreads();
    }
    int excl = (t > 0) ? s[t - 1] : 0;
    #pragma unroll
    for (int q = 0; q < 8; q++) {
        int idx = base + q;
        if (idx < N_NODES) g_off[idx] = v[q] + excl;
    }
    if (t == 255) g_bsum[b] = s[255];
}

__global__ void k_scan2() {
    __shared__ int s[512];
    int t = threadIdx.x;
    s[t] = (t < NB) ? g_bsum[t] : 0;
    __syncthreads();
    for (int o = 1; o < 512; o <<= 1) {
        int x = (t >= o) ? s[t - o] : 0;
        __syncthreads();
        s[t] += x;
        __syncthreads();
    }
    if (t < NB) g_bsum[t] = (t > 0) ? s[t - 1] : 0;   // exclusive
}

__global__ void k_scan3() {
    int i = blockIdx.x * blockDim.x + threadIdx.x;
    if (i < N_NODES) {
        int o = g_off[i] + g_bsum[i >> 11];
        g_off[i] = o;
        g_cur[i] = o;
    }
    if (i == 0) g_off[N_NODES] = N_EDGES;
}

__global__ void k_fill(const int4* __restrict__ src4, const int4* __restrict__ dst4) {
    int e = blockIdx.x * blockDim.x + threadIdx.x;
    if (e >= N_EDGES / 4) return;
    int4 s = src4[e];
    int4 d = dst4[e];
    g_csr[atomicAdd(&g_cur[d.x], 1)] = s.x;
    g_csr[atomicAdd(&g_cur[d.y], 1)] = s.y;
    g_csr[atomicAdd(&g_cur[d.z], 1)] = s.z;
    g_csr[atomicAdd(&g_cur[d.w], 1)] = s.w;
}

// ---------------------------------------------------------------------------
// K-mm1: msg1[i] = (embed[x[i]] @ W1) * dinv[i]  (half2-packed, 32 B/node)
__global__ void k_mm1(const int* __restrict__ x,
                      const float* __restrict__ embed,
                      const float* __restrict__ W1) {
    __shared__ float Ws[FDIM][FDIM];
    if (threadIdx.x < 256) {
        int k = threadIdx.x >> 4, j = threadIdx.x & 15;
        Ws[k][j] = W1[threadIdx.x];
    }
    __syncthreads();

    int i = blockIdx.x * blockDim.x + threadIdx.x;
    if (i >= N_NODES) return;

    const float4* rp = (const float4*)(embed + (size_t)x[i] * FDIM);
    float4 r0 = rp[0], r1 = rp[1], r2 = rp[2], r3 = rp[3];
    float row[FDIM] = {r0.x,r0.y,r0.z,r0.w, r1.x,r1.y,r1.z,r1.w,
                       r2.x,r2.y,r2.z,r2.w, r3.x,r3.y,r3.z,r3.w};
    float dv = g_dinv[i];
    float out[FDIM];
    #pragma unroll
    for (int j = 0; j < FDIM; j++) {
        float acc = 0.f;
        #pragma unroll
        for (int k = 0; k < FDIM; k++) acc = fmaf(row[k], Ws[k][j], acc);
        out[j] = acc * dv;
    }
    __half2 h[8];
    #pragma unroll
    for (int q = 0; q < 8; q++) h[q] = __floats2half2_rn(out[2*q], out[2*q+1]);
    uint4* mp = (uint4*)(g_msg1 + (size_t)i * 8);
    mp[0] = make_uint4(*(unsigned*)&h[0], *(unsigned*)&h[1], *(unsigned*)&h[2], *(unsigned*)&h[3]);
    mp[1] = make_uint4(*(unsigned*)&h[4], *(unsigned*)&h[5], *(unsigned*)&h[6], *(unsigned*)&h[7]);
}

// ---------------------------------------------------------------------------
// accumulate one uint4 (8 halfs) into 8 floats
__device__ __forceinline__ void acc_h8(float* a, uint4 m) {
    const unsigned* u = &m.x;
    #pragma unroll
    for (int q = 0; q < 4; q++) {
        float2 f = __half22float2(*(__half2*)&u[q]);
        a[2*q]     += f.x;
        a[2*q + 1] += f.y;
    }
}

// Gather core: 2 threads/node, uint4 loads, batches of 4 with clamped indices
// + predicated accumulate.
__device__ __forceinline__ void gather_acc8(float* acc, const uint4* __restrict__ M,
                                            int node, int t, int o0, int o1) {
    acc_h8(acc, M[(size_t)node * 2 + t]);          // self message

    int last = o1 - 1;
    for (int j = o0; j < o1; j += 4) {
        int j1 = min(j + 1, last), j2 = min(j + 2, last), j3 = min(j + 3, last);
        int s0 = g_csr[j],  s1 = g_csr[j1];
        int s2 = g_csr[j2], s3 = g_csr[j3];
        uint4 m0 = M[(size_t)s0 * 2 + t];
        uint4 m1 = M[(size_t)s1 * 2 + t];
        uint4 m2 = M[(size_t)s2 * 2 + t];
        uint4 m3 = M[(size_t)s3 * 2 + t];
        acc_h8(acc, m0);
        if (j + 1 < o1) acc_h8(acc, m1);
        if (j + 2 < o1) acc_h8(acc, m2);
        if (j + 3 < o1) acc_h8(acc, m3);
    }
}

// K-gather1 fused with layer-2 matmul. 2 threads/node, 128 nodes per block.
__global__ void k_gather_mm2(const float* __restrict__ W2,
                             const float* __restrict__ b1) {
    __shared__ float Ws[FDIM][FDIM];
    __shared__ float bs[FDIM];
    if (threadIdx.x < 256) {
        int k = threadIdx.x >> 4, j = threadIdx.x & 15;
        Ws[k][j] = W2[threadIdx.x];
        if (threadIdx.x < FDIM) bs[threadIdx.x] = b1[threadIdx.x];
    }
    __syncthreads();

    int node  = blockIdx.x * 128 + (threadIdx.x >> 1);
    if (node >= N_NODES) return;                    // warp-uniform (1e6 % 16 == 0)
    int t     = threadIdx.x & 1;
    int gbase = (threadIdx.x & 31) & ~1;

    float acc[8] = {0.f,0.f,0.f,0.f,0.f,0.f,0.f,0.f};
    gather_acc8(acc, (const uint4*)g_msg1, node, t,
                g_off[node], g_off[node + 1]);

    float dv = g_dinv[node];
    float h[8];
    #pragma unroll
    for (int q = 0; q < 8; q++)
        h[q] = fmaxf(fmaf(dv, acc[q], bs[8*t + q]), 0.f);

    float o[8] = {0.f,0.f,0.f,0.f,0.f,0.f,0.f,0.f};
    #pragma unroll
    for (int k = 0; k < FDIM; k++) {
        float hk = __shfl_sync(0xFFFFFFFFu, h[k & 7], gbase + (k >> 3));
        #pragma unroll
        for (int q = 0; q < 8; q++)
            o[q] = fmaf(hk, Ws[k][8*t + q], o[q]);
    }
    __half2 p[4];
    #pragma unroll
    for (int q = 0; q < 4; q++)
        p[q] = __floats2half2_rn(o[2*q] * dv, o[2*q + 1] * dv);
    ((uint4*)g_msg2)[(size_t)node * 2 + t] =
        make_uint4(*(unsigned*)&p[0], *(unsigned*)&p[1],
                   *(unsigned*)&p[2], *(unsigned*)&p[3]);
}

// K-gather2 fused with final FC partials, 2 threads/node.
__global__ void k_gather_z(const float* __restrict__ b2,
                           const float* __restrict__ fc_w) {
    __shared__ float bs[FDIM];
    __shared__ float fw[32];
    if (threadIdx.x < FDIM) bs[threadIdx.x] = b2[threadIdx.x];
    if (threadIdx.x < 32)   fw[threadIdx.x] = fc_w[threadIdx.x];
    __syncthreads();

    int node = blockIdx.x * 128 + (threadIdx.x >> 1);
    if (node >= N_NODES) return;                    // warp-uniform
    int t    = threadIdx.x & 1;

    float acc[8] = {0.f,0.f,0.f,0.f,0.f,0.f,0.f,0.f};
    gather_acc8(acc, (const uint4*)g_msg2, node, t,
                g_off[node], g_off[node + 1]);

    float dv = g_dinv[node];
    float pa = 0.f, pb = 0.f;
    #pragma unroll
    for (int q = 0; q < 8; q++) {
        float z = fmaf(dv, acc[q], bs[8*t + q]);
        pa = fmaf(z, fw[8*t + q],      pa);
        pb = fmaf(z, fw[16 + 8*t + q], pb);
    }
    pa += __shfl_xor_sync(0xFFFFFFFFu, pa, 1);
    pb += __shfl_xor_sync(0xFFFFFFFFu, pb, 1);

    if (t == 0) {
        g_pA[node] = pa;
        g_pB[node] = pb;
    }
}

// ---------------------------------------------------------------------------
// K-predict, 2 edges/thread with int2 index loads (N_LABEL even):
//   out[e] = pA[la[e]] + pB[lb[e]] + fc_b
__global__ void k_predict(const int2* __restrict__ la2,
                          const int2* __restrict__ lb2,
                          const float* __restrict__ fc_b,
                          float* __restrict__ out) {
    int i = blockIdx.x * blockDim.x + threadIdx.x;
    if (i >= N_LABEL / 2) return;
    float fb = __ldg(fc_b);
    int2 a = la2[i];
    int2 b = lb2[i];
    float r0 = g_pA[a.x] + g_pB[b.x] + fb;
    float r1 = g_pA[a.y] + g_pB[b.y] + fb;
    ((float2*)out)[i] = make_float2(r0, r1);
}

// ---------------------------------------------------------------------------
extern "C" void kernel_launch(void* const* d_in, const int* in_sizes, int n_in,
                              void* d_out, int out_size) {
    const int*   x     = (const int*)  d_in[0];
    const int*   ei    = (const int*)  d_in[1];
    const int*   eli   = (const int*)  d_in[2];
    const float* embed = (const float*)d_in[3];
    const float* W1    = (const float*)d_in[4];
    const float* b1    = (const float*)d_in[5];
    const float* W2    = (const float*)d_in[6];
    const float* b2    = (const float*)d_in[7];
    const float* fc_w  = (const float*)d_in[8];
    const float* fc_b  = (const float*)d_in[9];
    float*       out   = (float*)d_out;

    const int4* e_src4 = (const int4*)ei;
    const int4* e_dst4 = (const int4*)(ei + N_EDGES);
    const int2* l_a2   = (const int2*)eli;
    const int2* l_b2   = (const int2*)(eli + N_LABEL);

    const int TB = 256;
    int gN  = (N_NODES + TB - 1) / TB;
    int gE4 = (N_EDGES / 4 + TB - 1) / TB;
    int gL2 = (N_LABEL / 2 + TB - 1) / TB;
    int gG  = (N_NODES + 127) / 128;     // 7813 blocks, 2 thr/node

    static cudaStream_t s2 = nullptr;
    static cudaEvent_t  eA = nullptr, eB = nullptr, eC = nullptr;
    static void* degPtr = nullptr;
    if (!eA) {
        if (cudaStreamCreateWithFlags(&s2, cudaStreamNonBlocking) != cudaSuccess) s2 = nullptr;
        cudaEventCreateWithFlags(&eA, cudaEventDisableTiming);
        cudaEventCreateWithFlags(&eB, cudaEventDisableTiming);
        cudaEventCreateWithFlags(&eC, cudaEventDisableTiming);
        cudaGetSymbolAddress(&degPtr, g_deg);
    }

    // g_deg is zero here: static zero-init on the first call; trailing memset
    // (fully joined before graph end) restores it every run — graph-invariant.
    k_count<<<gE4, TB>>>(e_dst4);

    if (s2) {
        cudaEventRecord(eA, 0);            // "count done"
        cudaStreamWaitEvent(s2, eA, 0);
        k_dinv<<<gN, TB, 0, s2>>>();
        k_mm1 <<<gN, TB, 0, s2>>>(x, embed, W1);

        // main: CSR build
        k_scan1<<<NB, 256>>>();
        cudaEventRecord(eB, 0);            // "scan1 done" (last deg reader on main)
        k_scan2<<<1, 512>>>();
        k_scan3<<<gN, TB>>>();
        k_fill <<<gE4, TB>>>(e_src4, e_dst4);

        // side: after dinv+mm1 (deg readers) AND scan1, re-zero deg off-path
        cudaStreamWaitEvent(s2, eB, 0);
        cudaMemsetAsync(degPtr, 0, N_NODES * sizeof(int), s2);
        cudaEventRecord(eC, s2);           // records ALL side-stream work

        cudaStreamWaitEvent(0, eC, 0);     // full join — no dangling branch
    } else {
        k_dinv <<<gN, TB>>>();
        k_scan1<<<NB, 256>>>();
        k_scan2<<<1, 512>>>();
        k_scan3<<<gN, TB>>>();
        k_fill <<<gE4, TB>>>(e_src4, e_dst4);
        k_mm1  <<<gN, TB>>>(x, embed, W1);
        cudaMemsetAsync(degPtr, 0, N_NODES * sizeof(int), 0);
    }

    k_gather_mm2<<<gG, TB>>>(W2, b1);
    k_gather_z  <<<gG, TB>>>(b2, fc_w);
    k_predict   <<<gL2, TB>>>(l_a2, l_b2, fc_b, out);
}